// round 2
// baseline (speedup 1.0000x reference)
#include <cuda_runtime.h>

#define B 16
#define C 256
#define O_CH 256
#define H 128
#define W 128
#define G 32
#define CG 8
#define OG 8
#define HW (H*W)
#define TILE 32
#define TROWS 34
#define TPITCH 36   // padded row pitch (floats) so float4 loads stay 16B-aligned

typedef unsigned long long u64;

__device__ float d_mean[B*C];
__device__ float d_inv[B*C];
__device__ float d_comb[B*O_CH*CG*9];

__device__ __forceinline__ u64 pk(float lo, float hi) {
    u64 r; asm("mov.b64 %0,{%1,%2};" : "=l"(r) : "f"(lo), "f"(hi)); return r;
}
__device__ __forceinline__ float2 upk(u64 a) {
    float2 f; asm("mov.b64 {%0,%1},%2;" : "=f"(f.x), "=f"(f.y) : "l"(a)); return f;
}
__device__ __forceinline__ u64 ffma2(u64 a, u64 b, u64 c) {
    u64 d; asm("fma.rn.f32x2 %0,%1,%2,%3;" : "=l"(d) : "l"(a), "l"(b), "l"(c)); return d;
}

// ---------------------------------------------------------------------------
// Kernel 1: per-(b,c) instance-norm stats (mean, 1/(std_ddof1 + eps)).
// ---------------------------------------------------------------------------
__global__ __launch_bounds__(256) void stats_kernel(const float* __restrict__ x) {
    int idx = blockIdx.x;
    const float4* p = (const float4*)(x + (size_t)idx * HW);
    float s0 = 0.f, s1 = 0.f, q0 = 0.f, q1 = 0.f;
    #pragma unroll 4
    for (int i = threadIdx.x; i < HW/8; i += 256) {
        float4 a = p[i];
        float4 b = p[i + HW/8];
        s0 += a.x + a.y + a.z + a.w;
        q0 += a.x*a.x + a.y*a.y + a.z*a.z + a.w*a.w;
        s1 += b.x + b.y + b.z + b.w;
        q1 += b.x*b.x + b.y*b.y + b.z*b.z + b.w*b.w;
    }
    float s = s0 + s1, ss = q0 + q1;
    #pragma unroll
    for (int o = 16; o > 0; o >>= 1) {
        s  += __shfl_down_sync(0xffffffffu, s,  o);
        ss += __shfl_down_sync(0xffffffffu, ss, o);
    }
    __shared__ float as[8], bs[8];
    int lane = threadIdx.x & 31, wid = threadIdx.x >> 5;
    if (lane == 0) { as[wid] = s; bs[wid] = ss; }
    __syncthreads();
    if (threadIdx.x == 0) {
        float S = 0.f, SS = 0.f;
        #pragma unroll
        for (int w = 0; w < 8; w++) { S += as[w]; SS += bs[w]; }
        float mean = S * (1.0f / HW);
        float var  = (SS - S * mean) * (1.0f / (HW - 1));
        var = fmaxf(var, 0.0f);
        d_mean[idx] = mean;
        d_inv[idx]  = 1.0f / (sqrtf(var) + 1e-7f);
    }
}

// ---------------------------------------------------------------------------
// Kernel 2: fold grouped 1x1 conv into the 3x3 weights.
// ---------------------------------------------------------------------------
__global__ void combine_kernel(const float* __restrict__ dw,
                               const float* __restrict__ pw) {
    int bo = blockIdx.x;
    int t  = threadIdx.x;          // 0..71
    int o  = bo % O_CH;
    int b  = bo / O_CH;
    int g  = o >> 3;
    int i  = t / 9, tap = t % 9;
    const float* pwp = pw + (size_t)bo * OG;
    float acc = 0.f;
    #pragma unroll
    for (int ip = 0; ip < 8; ip++)
        acc += pwp[ip] * dw[(((size_t)b*O_CH + (g*OG + ip))*CG + i)*9 + tap];
    d_comb[(size_t)bo*72 + t] = acc;
}

// ---------------------------------------------------------------------------
// Kernel 3: fused norm + grouped 3x3 conv + bias, packed f32x2 math.
// Block = (b, g, 32x32 tile). 256 threads: thread -> 1 row, 4 adjacent cols.
// ---------------------------------------------------------------------------
__global__ __launch_bounds__(256) void conv_kernel(const float* __restrict__ x,
                                                   const float* __restrict__ biases,
                                                   float* __restrict__ out) {
    __shared__ float tile[CG][TROWS * TPITCH];   // 39168 B
    __shared__ u64   ws2[OG*CG*9];               // weights duplicated (w,w), 4608 B
    __shared__ float smean[CG], sinv[CG];

    int b  = blockIdx.z;
    int g  = blockIdx.y;
    int tx = (blockIdx.x & 3) * TILE;
    int ty = (blockIdx.x >> 2) * TILE;
    int tid = threadIdx.x;

    if (tid < CG) {
        smean[tid] = d_mean[b*C + g*CG + tid];
        sinv[tid]  = d_inv [b*C + g*CG + tid];
    }
    __syncthreads();

    {   // duplicate weights into packed (w,w) form
        const float* cb = d_comb + ((size_t)b*O_CH + g*OG) * 72;
        for (int idx = tid; idx < OG*CG*9; idx += 256) {
            float w = cb[idx];
            ws2[idx] = pk(w, w);
        }
    }

    {   // load + normalize 8 channel tiles, 34x34 with 1-px zero halo
        const float* xb = x + (size_t)(b*C + g*CG) * HW;
        for (int idx = tid; idx < CG*TROWS*TROWS; idx += 256) {
            int ch = idx / (TROWS*TROWS);
            int rr = idx % (TROWS*TROWS);
            int r  = rr / TROWS, cc = rr % TROWS;
            int gh = ty + r - 1, gw = tx + cc - 1;
            float v = 0.f;
            if ((unsigned)gh < (unsigned)H && (unsigned)gw < (unsigned)W)
                v = (xb[(size_t)ch*HW + gh*W + gw] - smean[ch]) * sinv[ch];
            tile[ch][r*TPITCH + cc] = v;
        }
    }
    __syncthreads();

    int c4 = (tid & 7) * 4;      // first of 4 adjacent output columns
    int r  = tid >> 3;           // output row 0..31

    u64 acc[OG][2];
    #pragma unroll
    for (int o = 0; o < OG; o++) { acc[o][0] = 0ull; acc[o][1] = 0ull; }

    #pragma unroll
    for (int i = 0; i < CG; i++) {
        #pragma unroll
        for (int kh = 0; kh < 3; kh++) {
            const float* rp = &tile[i][(r + kh)*TPITCH + c4];
            float4 q  = *(const float4*)rp;        // x[c-1..c+2]
            float2 t2 = *(const float2*)(rp + 4);  // x[c+3..c+4]
            u64 pA = pk(q.x, q.y);                 // kw0 lo
            u64 pB = pk(q.y, q.z);                 // kw1 lo
            u64 pC = pk(q.z, q.w);                 // kw0 hi / kw2 lo
            u64 pD = pk(q.w, t2.x);                // kw1 hi
            u64 pE = pk(t2.x, t2.y);               // kw2 hi
            const u64* wb = &ws2[i*9 + kh*3];
            #pragma unroll
            for (int o = 0; o < OG; o++) {
                u64 w0 = wb[o*72 + 0];
                u64 w1 = wb[o*72 + 1];
                u64 w2 = wb[o*72 + 2];
                acc[o][0] = ffma2(w0, pA, acc[o][0]);
                acc[o][1] = ffma2(w0, pC, acc[o][1]);
                acc[o][0] = ffma2(w1, pB, acc[o][0]);
                acc[o][1] = ffma2(w1, pD, acc[o][1]);
                acc[o][0] = ffma2(w2, pC, acc[o][0]);
                acc[o][1] = ffma2(w2, pE, acc[o][1]);
            }
        }
    }

    float* ob = out + (size_t)(b*O_CH + g*OG) * HW + (size_t)(ty + r)*W + tx + c4;
    #pragma unroll
    for (int o = 0; o < OG; o++) {
        float bi = biases[b*O_CH + g*OG + o];
        float2 a0 = upk(acc[o][0]);
        float2 a1 = upk(acc[o][1]);
        float4 v = make_float4(a0.x + bi, a0.y + bi, a1.x + bi, a1.y + bi);
        *(float4*)(ob + (size_t)o*HW) = v;
    }
}

// ---------------------------------------------------------------------------
extern "C" void kernel_launch(void* const* d_in, const int* in_sizes, int n_in,
                              void* d_out, int out_size) {
    const float* x      = (const float*)d_in[0];
    const float* dw     = (const float*)d_in[1];
    const float* pw     = (const float*)d_in[2];
    const float* biases = (const float*)d_in[3];
    float* out = (float*)d_out;

    stats_kernel<<<B*C, 256>>>(x);
    combine_kernel<<<B*O_CH, 72>>>(dw, pw);
    conv_kernel<<<dim3(16, G, B), 256>>>(x, biases, out);
}

// round 4
// speedup vs baseline: 2.1524x; 2.1524x over previous
#include <cuda_runtime.h>
#include <cuda_fp16.h>
#include <cstdint>

#define B 16
#define C 256
#define O_CH 256
#define H 128
#define W 128
#define G 32
#define CG 8
#define OG 8
#define HW (H*W)

#define RSTRIP 8          // output rows per CTA
#define TROWS (RSTRIP+2)  // staged rows incl. halo
#define TC 132            // padded col count (cols 0..129 used)

__device__ float d_mean[B*C];
__device__ float d_inv[B*C];
__device__ float d_comb[B*O_CH*CG*9];

__device__ __forceinline__ uint32_t pkh2(float a, float b) {
    __half2 h = __floats2half2_rn(a, b);
    return *reinterpret_cast<uint32_t*>(&h);
}

// ---------------------------------------------------------------------------
// Kernel 1: per-(b,c) instance-norm stats.
// ---------------------------------------------------------------------------
__global__ __launch_bounds__(256) void stats_kernel(const float* __restrict__ x) {
    int idx = blockIdx.x;
    const float4* p = (const float4*)(x + (size_t)idx * HW);
    float s0 = 0.f, s1 = 0.f, q0 = 0.f, q1 = 0.f;
    #pragma unroll 4
    for (int i = threadIdx.x; i < HW/8; i += 256) {
        float4 a = p[i];
        float4 b = p[i + HW/8];
        s0 += a.x + a.y + a.z + a.w;
        q0 += a.x*a.x + a.y*a.y + a.z*a.z + a.w*a.w;
        s1 += b.x + b.y + b.z + b.w;
        q1 += b.x*b.x + b.y*b.y + b.z*b.z + b.w*b.w;
    }
    float s = s0 + s1, ss = q0 + q1;
    #pragma unroll
    for (int o = 16; o > 0; o >>= 1) {
        s  += __shfl_down_sync(0xffffffffu, s,  o);
        ss += __shfl_down_sync(0xffffffffu, ss, o);
    }
    __shared__ float as[8], bs[8];
    int lane = threadIdx.x & 31, wid = threadIdx.x >> 5;
    if (lane == 0) { as[wid] = s; bs[wid] = ss; }
    __syncthreads();
    if (threadIdx.x == 0) {
        float S = 0.f, SS = 0.f;
        #pragma unroll
        for (int w = 0; w < 8; w++) { S += as[w]; SS += bs[w]; }
        float mean = S * (1.0f / HW);
        float var  = (SS - S * mean) * (1.0f / (HW - 1));
        var = fmaxf(var, 0.0f);
        d_mean[idx] = mean;
        d_inv[idx]  = 1.0f / (sqrtf(var) + 1e-7f);
    }
}

// ---------------------------------------------------------------------------
// Kernel 2: fold grouped 1x1 conv into the 3x3 weights.
// comb[b][o][i][tap] = sum_ip pw[b][o][ip] * dw[b][g*8+ip][i][tap]
// ---------------------------------------------------------------------------
__global__ void combine_kernel(const float* __restrict__ dw,
                               const float* __restrict__ pw) {
    int bo = blockIdx.x;
    int t  = threadIdx.x;          // 0..71
    int o  = bo % O_CH;
    int b  = bo / O_CH;
    int g  = o >> 3;
    int i  = t / 9, tap = t % 9;
    const float* pwp = pw + (size_t)bo * OG;
    float acc = 0.f;
    #pragma unroll
    for (int ip = 0; ip < 8; ip++)
        acc += pwp[ip] * dw[(((size_t)b*O_CH + (g*OG + ip))*CG + i)*9 + tap];
    d_comb[(size_t)bo*72 + t] = acc;
}

// ---------------------------------------------------------------------------
// Kernel 3: fused norm + grouped 3x3 conv + bias via fp16 mma.sync (HMMA).
// CTA = (b, g, 8-row strip). Implicit GEMM: D[px,8] = A[px,72] x W[72,8].
// K layout: k = tap*8 + ch, tap = kh*3+kw. Warp wi owns output row r0+wi,
// iterating 8 x 16-pixel m-tiles: 4x m16n8k16 + 1x m16n8k8 per tile.
// ---------------------------------------------------------------------------
__global__ __launch_bounds__(256, 1) void conv_kernel(const float* __restrict__ x,
                                                      const float* __restrict__ biases,
                                                      float* __restrict__ out) {
    __shared__ __align__(16) __half tile[TROWS][TC][CG];   // 21120 B
    __shared__ float wsm[OG*72];                           // 2304 B

    int b  = blockIdx.z;
    int g  = blockIdx.y;
    int r0 = blockIdx.x * RSTRIP;
    int tid  = threadIdx.x;
    int lane = tid & 31;
    int wi   = tid >> 5;          // warp id = local output row

    // ---- stage combined weights ----
    {
        const float* cb = d_comb + (size_t)(b*O_CH + g*OG) * 72;
        for (int idx = tid; idx < OG*72; idx += 256) wsm[idx] = cb[idx];
    }

    // ---- stage normalized fp16 input tile (10 rows x 130 cols x 8 ch) ----
    {
        float m8[CG], i8[CG];
        #pragma unroll
        for (int ch = 0; ch < CG; ch++) {
            m8[ch] = d_mean[b*C + g*CG + ch];
            i8[ch] = d_inv [b*C + g*CG + ch];
        }
        const float* xb = x + (size_t)(b*C + g*CG) * HW;
        #pragma unroll
        for (int it = 0; it < (TROWS*W)/256; it++) {
            int p    = tid + it * 256;
            int row  = p >> 7;           // 0..9
            int w    = p & 127;
            int grow = r0 - 1 + row;
            uint32_t h0 = 0, h1 = 0, h2 = 0, h3 = 0;
            if ((unsigned)grow < (unsigned)H) {
                const float* px = xb + (size_t)grow * W + w;
                float v0 = (px[0*HW] - m8[0]) * i8[0];
                float v1 = (px[1*HW] - m8[1]) * i8[1];
                float v2 = (px[2*HW] - m8[2]) * i8[2];
                float v3 = (px[3*HW] - m8[3]) * i8[3];
                float v4 = (px[4*HW] - m8[4]) * i8[4];
                float v5 = (px[5*HW] - m8[5]) * i8[5];
                float v6 = (px[6*HW] - m8[6]) * i8[6];
                float v7 = (px[7*HW] - m8[7]) * i8[7];
                h0 = pkh2(v0, v1); h1 = pkh2(v2, v3);
                h2 = pkh2(v4, v5); h3 = pkh2(v6, v7);
            }
            *(uint4*)&tile[row][w + 1][0] = make_uint4(h0, h1, h2, h3);
        }
        // zero halo columns 0 and 129
        if (tid < TROWS * 2) {
            int row = tid >> 1;
            int col = (tid & 1) ? 129 : 0;
            *(uint4*)&tile[row][col][0] = make_uint4(0u, 0u, 0u, 0u);
        }
    }
    __syncthreads();

    // ---- per-thread B fragments (weights), built once ----
    // b-frag mapping (m16n8k16): n = lane>>2, k = (lane&3)*2 (+1) [+8] [+16j]
    int gid = lane >> 2;   // groupID: A row (pixel), B col (n), D row
    int tg  = lane & 3;    // threadID in group
    uint32_t bf[9];
    {
        const float* wn = wsm + gid * 72 + (tg * 2) * 9;  // [ch=tg*2][tap], next ch at +9
        #pragma unroll
        for (int j = 0; j < 4; j++) {
            bf[2*j + 0] = pkh2(wn[2*j],     wn[9 + 2*j]);       // tap 2j,   ch pair
            bf[2*j + 1] = pkh2(wn[2*j + 1], wn[9 + 2*j + 1]);   // tap 2j+1, ch pair
        }
        bf[8] = pkh2(wn[8], wn[17]);                             // tap 8
    }

    float bia0 = biases[b*O_CH + g*OG + tg*2];
    float bia1 = biases[b*O_CH + g*OG + tg*2 + 1];

    int h = r0 + wi;
    float* obase = out + (size_t)(b*O_CH + g*OG + tg*2) * HW + (size_t)h * W;

    #pragma unroll
    for (int ws = 0; ws < 8; ws++) {
        int w16 = ws * 16;
        float d0 = 0.f, d1 = 0.f, d2 = 0.f, d3 = 0.f;

        #pragma unroll
        for (int j = 0; j < 4; j++) {
            int tA = 2*j, tB = 2*j + 1;
            const __half* pA = &tile[wi + tA/3][w16 + gid + tA%3][tg*2];
            const __half* pB = &tile[wi + tB/3][w16 + gid + tB%3][tg*2];
            uint32_t a0 = *(const uint32_t*)pA;          // (w,     tapA)
            uint32_t a1 = *(const uint32_t*)(pA + 64);   // (w+8,   tapA)
            uint32_t a2 = *(const uint32_t*)pB;          // (w,     tapB)
            uint32_t a3 = *(const uint32_t*)(pB + 64);   // (w+8,   tapB)
            asm volatile(
                "mma.sync.aligned.m16n8k16.row.col.f32.f16.f16.f32 "
                "{%0,%1,%2,%3},{%4,%5,%6,%7},{%8,%9},{%0,%1,%2,%3};"
                : "+f"(d0), "+f"(d1), "+f"(d2), "+f"(d3)
                : "r"(a0), "r"(a1), "r"(a2), "r"(a3),
                  "r"(bf[2*j]), "r"(bf[2*j + 1]));
        }
        {   // tap 8 (kh=2, kw=2), K-remainder of 8
            const __half* pA = &tile[wi + 2][w16 + gid + 2][tg*2];
            uint32_t a0 = *(const uint32_t*)pA;
            uint32_t a1 = *(const uint32_t*)(pA + 64);
            asm volatile(
                "mma.sync.aligned.m16n8k8.row.col.f32.f16.f16.f32 "
                "{%0,%1,%2,%3},{%4,%5},{%6},{%0,%1,%2,%3};"
                : "+f"(d0), "+f"(d1), "+f"(d2), "+f"(d3)
                : "r"(a0), "r"(a1), "r"(bf[8]));
        }

        // D mapping: d0=(w16+gid, o=tg*2) d1=(., o+1) d2=(w16+gid+8, o) d3=(., o+1)
        float* ob = obase + w16 + gid;
        ob[0]      = d0 + bia0;
        ob[HW]     = d1 + bia1;
        ob[8]      = d2 + bia0;
        ob[HW + 8] = d3 + bia1;
    }
}

// ---------------------------------------------------------------------------
extern "C" void kernel_launch(void* const* d_in, const int* in_sizes, int n_in,
                              void* d_out, int out_size) {
    const float* x      = (const float*)d_in[0];
    const float* dw     = (const float*)d_in[1];
    const float* pw     = (const float*)d_in[2];
    const float* biases = (const float*)d_in[3];
    float* out = (float*)d_out;

    combine_kernel<<<B*O_CH, 72>>>(dw, pw);
    stats_kernel<<<B*C, 256>>>(x);
    conv_kernel<<<dim3(H/RSTRIP, G, B), 256>>>(x, biases, out);
}

// round 5
// speedup vs baseline: 2.3253x; 1.0803x over previous
#include <cuda_runtime.h>
#include <cuda_fp16.h>
#include <cstdint>

#define B 16
#define C 256
#define O_CH 256
#define H 128
#define W 128
#define G 32
#define CG 8
#define OG 8
#define HW (H*W)

#define RSTRIP 16
#define TROWS (RSTRIP+2)   // 18 staged rows
#define TC 132             // padded cols: 0..129 used
#define NTASK (TROWS*16)   // 288 staging tasks (8 px each)

__device__ float d_mean[B*C];
__device__ float d_inv[B*C];
__device__ float d_comb[B*O_CH*CG*9];   // norm-folded weights W' = W*inv
__device__ float d_bias2[B*O_CH];       // bias' = bias - sum W'*mean

__device__ __forceinline__ uint32_t pkh2(float a, float b) {
    __half2 h = __floats2half2_rn(a, b);
    return *reinterpret_cast<uint32_t*>(&h);
}
__device__ __forceinline__ uint32_t smem_u32(const void* p) {
    uint32_t a;
    asm("{ .reg .u64 t; cvta.to.shared.u64 t, %1; cvt.u32.u64 %0, t; }" : "=r"(a) : "l"(p));
    return a;
}
// swizzle on 16B units: keeps STS.128 (stride-8) and ldmatrix rows conflict-free
__device__ __forceinline__ uint32_t SW(uint32_t a16) { return a16 ^ ((a16 >> 3) & 7u); }

__device__ __forceinline__ void sts128(uint32_t addr, uint32_t a, uint32_t b, uint32_t c, uint32_t d) {
    asm volatile("st.shared.v4.b32 [%0], {%1,%2,%3,%4};" :: "r"(addr), "r"(a), "r"(b), "r"(c), "r"(d) : "memory");
}

// ---------------------------------------------------------------------------
// Kernel 1: per-(b,c) instance-norm stats.
// ---------------------------------------------------------------------------
__global__ __launch_bounds__(256) void stats_kernel(const float* __restrict__ x) {
    int idx = blockIdx.x;
    const float4* p = (const float4*)(x + (size_t)idx * HW);
    float s0 = 0.f, s1 = 0.f, q0 = 0.f, q1 = 0.f;
    #pragma unroll 4
    for (int i = threadIdx.x; i < HW/8; i += 256) {
        float4 a = p[i];
        float4 b = p[i + HW/8];
        s0 += a.x + a.y + a.z + a.w;
        q0 += a.x*a.x + a.y*a.y + a.z*a.z + a.w*a.w;
        s1 += b.x + b.y + b.z + b.w;
        q1 += b.x*b.x + b.y*b.y + b.z*b.z + b.w*b.w;
    }
    float s = s0 + s1, ss = q0 + q1;
    #pragma unroll
    for (int o = 16; o > 0; o >>= 1) {
        s  += __shfl_down_sync(0xffffffffu, s,  o);
        ss += __shfl_down_sync(0xffffffffu, ss, o);
    }
    __shared__ float as[8], bs[8];
    int lane = threadIdx.x & 31, wid = threadIdx.x >> 5;
    if (lane == 0) { as[wid] = s; bs[wid] = ss; }
    __syncthreads();
    if (threadIdx.x == 0) {
        float S = 0.f, SS = 0.f;
        #pragma unroll
        for (int w = 0; w < 8; w++) { S += as[w]; SS += bs[w]; }
        float mean = S * (1.0f / HW);
        float var  = (SS - S * mean) * (1.0f / (HW - 1));
        var = fmaxf(var, 0.0f);
        d_mean[idx] = mean;
        d_inv[idx]  = 1.0f / (sqrtf(var) + 1e-7f);
    }
}

// ---------------------------------------------------------------------------
// Kernel 2: fold 1x1 conv AND instance-norm into 3x3 weights + bias.
// W'[o,i,tap] = (sum_ip pw[o,ip]*dw[g8+ip,i,tap]) * inv[i]
// bias'[o]    = bias[o] - sum_{i,tap} W'[o,i,tap] * mean[i]
// ---------------------------------------------------------------------------
__global__ void combine_kernel(const float* __restrict__ dw,
                               const float* __restrict__ pw,
                               const float* __restrict__ biases) {
    __shared__ float red[72];
    int bo = blockIdx.x;
    int t  = threadIdx.x;          // 0..71
    int o  = bo % O_CH;
    int b  = bo / O_CH;
    int g  = o >> 3;
    int i  = t / 9, tap = t % 9;
    const float* pwp = pw + (size_t)bo * OG;
    float acc = 0.f;
    #pragma unroll
    for (int ip = 0; ip < 8; ip++)
        acc += pwp[ip] * dw[(((size_t)b*O_CH + (g*OG + ip))*CG + i)*9 + tap];
    float inv_i  = d_inv [b*C + g*CG + i];
    float mean_i = d_mean[b*C + g*CG + i];
    float wp = acc * inv_i;
    d_comb[(size_t)bo*72 + t] = wp;
    red[t] = wp * mean_i;
    __syncthreads();
    if (t == 0) {
        float s = 0.f;
        #pragma unroll
        for (int k = 0; k < 72; k++) s += red[k];
        d_bias2[bo] = biases[bo] - s;
    }
}

// ---------------------------------------------------------------------------
// Kernel 3: grouped 3x3 conv (norm folded into weights) via HMMA + ldmatrix.
// CTA = (b, g, 16-row strip), 512 threads / 16 warps (1 output row each).
// smem tile: [18 rows][132 cols][8 ch] fp16, 16B-unit XOR swizzle.
// ---------------------------------------------------------------------------
__global__ __launch_bounds__(512, 2) void conv_kernel(const float* __restrict__ x,
                                                      float* __restrict__ out) {
    __shared__ __align__(16) __half tile[TROWS*TC*CG];   // 38016 B
    __shared__ float wsm[OG*72];
    __shared__ float smean[CG];

    int b  = blockIdx.z;
    int g  = blockIdx.y;
    int r0 = blockIdx.x * RSTRIP;
    int tid  = threadIdx.x;
    int lane = tid & 31;
    int wi   = tid >> 5;

    uint32_t sb = smem_u32(tile);

    if (tid < CG) smean[tid] = d_mean[b*C + g*CG + tid];
    {
        const float* cb = d_comb + (size_t)(b*O_CH + g*OG) * 72;
        for (int idx = tid; idx < OG*72; idx += 512) wsm[idx] = cb[idx];
    }
    __syncthreads();

    // ---- staging: task = 8 px x 8 ch -> transpose -> 8 STS.128 ----
    if (tid < NTASK) {
        int row = tid >> 4;
        int w0  = (tid & 15) << 3;
        int grow = r0 - 1 + row;
        uint32_t h[CG][4];
        if ((unsigned)grow < (unsigned)H) {
            const float* xb = x + (size_t)(b*C + g*CG) * HW + (size_t)grow * W + w0;
            #pragma unroll
            for (int ch = 0; ch < CG; ch++) {
                const float4* p = (const float4*)(xb + (size_t)ch * HW);
                float4 A0 = p[0], A1 = p[1];
                h[ch][0] = pkh2(A0.x, A0.y);
                h[ch][1] = pkh2(A0.z, A0.w);
                h[ch][2] = pkh2(A1.x, A1.y);
                h[ch][3] = pkh2(A1.z, A1.w);
            }
        } else {
            #pragma unroll
            for (int ch = 0; ch < CG; ch++) {
                uint32_t mm = pkh2(smean[ch], smean[ch]);
                h[ch][0] = mm; h[ch][1] = mm; h[ch][2] = mm; h[ch][3] = mm;
            }
        }
        #pragma unroll
        for (int p = 0; p < 8; p++) {
            uint32_t sel = (p & 1) ? 0x7632u : 0x5410u;
            int i2 = p >> 1;
            uint32_t q0 = __byte_perm(h[0][i2], h[1][i2], sel);
            uint32_t q1 = __byte_perm(h[2][i2], h[3][i2], sel);
            uint32_t q2 = __byte_perm(h[4][i2], h[5][i2], sel);
            uint32_t q3 = __byte_perm(h[6][i2], h[7][i2], sel);
            uint32_t a16 = (uint32_t)(row*TC + w0 + 1 + p);
            sts128(sb + SW(a16)*16u, q0, q1, q2, q3);
        }
    } else if (tid < NTASK + 36) {
        // halo columns 0 and 129: padded pixel -> raw value = mean (xn = 0)
        int idx = tid - NTASK;
        int row = idx >> 1;
        int col = (idx & 1) ? 129 : 0;
        uint32_t q0 = pkh2(smean[0], smean[1]);
        uint32_t q1 = pkh2(smean[2], smean[3]);
        uint32_t q2 = pkh2(smean[4], smean[5]);
        uint32_t q3 = pkh2(smean[6], smean[7]);
        uint32_t a16 = (uint32_t)(row*TC + col);
        sts128(sb + SW(a16)*16u, q0, q1, q2, q3);
    }
    __syncthreads();

    // ---- B fragments (weights) ----
    int gid = lane >> 2;   // n index: output channel o = gid; also A/D row (px)
    int tg  = lane & 3;    // k group: ch pair tg*2
    uint32_t bf[9];
    {
        const float* wn = wsm + gid * 72 + (tg * 2) * 9;
        #pragma unroll
        for (int j = 0; j < 4; j++) {
            bf[2*j + 0] = pkh2(wn[2*j],     wn[9 + 2*j]);
            bf[2*j + 1] = pkh2(wn[2*j + 1], wn[9 + 2*j + 1]);
        }
        bf[8] = pkh2(wn[8], wn[17]);
    }

    // ---- per-thread ldmatrix base offsets (16B units, before swizzle) ----
    int q  = lane >> 3;            // 0..3
    int l8 = lane & 7;
    int base_j[4], base_8;
    #pragma unroll
    for (int j = 0; j < 4; j++) {
        int t = 2*j + (q >> 1);
        base_j[j] = (wi + t/3)*TC + (q & 1)*8 + l8 + (t % 3);
    }
    base_8 = (wi + 2)*TC + (q & 1)*8 + l8 + 2;

    float bia0 = d_bias2[b*O_CH + g*OG + gid];   // note: D col = n = gid? no:
    // D mapping (m16n8): row = gid (px), col = tg*2 (o). B col n = gid holds W'[o=n].
    // -> output channel for d0/d1 is tg*2 / tg*2+1. Load those biases:
    bia0 = d_bias2[b*O_CH + g*OG + tg*2];
    float bia1 = d_bias2[b*O_CH + g*OG + tg*2 + 1];

    int hrow = r0 + wi;
    float* obase = out + (size_t)(b*O_CH + g*OG + tg*2) * HW + (size_t)hrow * W;

    #pragma unroll
    for (int ws = 0; ws < 8; ws++) {
        int w16 = ws * 16;
        float d0 = 0.f, d1 = 0.f, d2 = 0.f, d3 = 0.f;

        #pragma unroll
        for (int j = 0; j < 4; j++) {
            uint32_t a16 = (uint32_t)(base_j[j] + w16);
            uint32_t addr = sb + SW(a16)*16u;
            uint32_t a0, a1, a2, a3;
            asm volatile("ldmatrix.sync.aligned.m8n8.x4.shared.b16 {%0,%1,%2,%3}, [%4];"
                         : "=r"(a0), "=r"(a1), "=r"(a2), "=r"(a3) : "r"(addr));
            asm volatile(
                "mma.sync.aligned.m16n8k16.row.col.f32.f16.f16.f32 "
                "{%0,%1,%2,%3},{%4,%5,%6,%7},{%8,%9},{%0,%1,%2,%3};"
                : "+f"(d0), "+f"(d1), "+f"(d2), "+f"(d3)
                : "r"(a0), "r"(a1), "r"(a2), "r"(a3),
                  "r"(bf[2*j]), "r"(bf[2*j + 1]));
        }
        {
            uint32_t a16 = (uint32_t)(base_8 + w16);
            uint32_t addr = sb + SW(a16)*16u;
            uint32_t a0, a1;
            asm volatile("ldmatrix.sync.aligned.m8n8.x2.shared.b16 {%0,%1}, [%2];"
                         : "=r"(a0), "=r"(a1) : "r"(addr));
            asm volatile(
                "mma.sync.aligned.m16n8k8.row.col.f32.f16.f16.f32 "
                "{%0,%1,%2,%3},{%4,%5},{%6},{%0,%1,%2,%3};"
                : "+f"(d0), "+f"(d1), "+f"(d2), "+f"(d3)
                : "r"(a0), "r"(a1), "r"(bf[8]));
        }

        float* ob = obase + w16 + gid;
        ob[0]      = d0 + bia0;
        ob[HW]     = d1 + bia1;
        ob[8]      = d2 + bia0;
        ob[HW + 8] = d3 + bia1;
    }
}

// ---------------------------------------------------------------------------
extern "C" void kernel_launch(void* const* d_in, const int* in_sizes, int n_in,
                              void* d_out, int out_size) {
    const float* x      = (const float*)d_in[0];
    const float* dw     = (const float*)d_in[1];
    const float* pw     = (const float*)d_in[2];
    const float* biases = (const float*)d_in[3];
    float* out = (float*)d_out;

    stats_kernel<<<B*C, 256>>>(x);
    combine_kernel<<<B*O_CH, 72>>>(dw, pw, biases);
    conv_kernel<<<dim3(H/RSTRIP, G, B), 512>>>(x, out);
}